// round 7
// baseline (speedup 1.0000x reference)
#include <cuda_runtime.h>
#include <cuda_fp16.h>
#include <math.h>
#include <stdint.h>

// ---------------- problem constants ----------------
#define BSZ   64
#define HD    1024
#define ED    512
#define SRCL  128
#define TGTL  128
#define NBLK  256
#define NTHR  256
#define OUT_MAIN (TGTL*BSZ*HD)

// ---------------- SMEM layout ----------------
#define ABUF(buf,pl) ((buf)*49152 + (pl)*16384)
#define BBUF(buf,pl) ((buf)*49152 + 32768 + (pl)*8192)
#define OFF_LG     98304
#define OFF_RV     (OFF_LG + 4096)
#define OFF_RI     (OFF_RV + 1024)
#define OFF_RS     (OFF_RI + 1024)
#define OFF_STEPV  (OFF_RS + 1024)
#define SMEM_TOTAL (OFF_STEPV + 512 + 128)   // ~104KB -> 2 blocks/SM

#define SW(o) ((o) ^ (((o) >> 3) & 0x70))

// ---------------- device scratch (static, no allocs) ----------------
__device__ __half g_e0w1[4096*1536], g_e0w2[4096*1536];   // gate-interleaved rows
__device__ __half g_e1w1[4096*2048], g_e1w2[4096*2048];
__device__ __half g_d0w1[4096*1536], g_d0w2[4096*1536];
__device__ __half g_d1w1[4096*2048], g_d1w2[4096*2048];
__device__ __half g_lnw1[1024*1024], g_lnw2[1024*1024];   // identity rows
__device__ float  g_be0[4096], g_be1[4096], g_bd0[4096], g_bd1[4096]; // packed biases
__device__ __half g_xe1[SRCL*BSZ*ED], g_xe2[SRCL*BSZ*ED];
__device__ __half g_xd1[BSZ*ED], g_xd2[BSZ*ED];
__device__ __half g_h0p1[BSZ*HD], g_h0p2[BSZ*HD];
__device__ __half g_h1p1[BSZ*HD], g_h1p2[BSZ*HD];
__device__ float  g_c0f[BSZ*HD], g_c1f[BSZ*HD];
__device__ float  g_zpart[2097152];        // cells: [jt32][ks8][128][64]; logits: [jt8][ks16][128][64]
__device__ float  g_nll[TGTL*BSZ];
__device__ unsigned g_jcnt[32];
__device__ unsigned g_cnt;
__device__ volatile unsigned g_gen;

// ---------------- helpers ----------------
__device__ __forceinline__ float sigm(float x) { return 1.0f / (1.0f + expf(-x)); }
__device__ __forceinline__ uint32_t smem_u32(const void* p) {
    uint32_t a;
    asm("{ .reg .u64 t; cvta.to.shared.u64 t, %1; cvt.u32.u64 %0, t; }" : "=r"(a) : "l"(p));
    return a;
}
__device__ __forceinline__ void cp_async16(uint32_t dst, const void* src) {
    asm volatile("cp.async.cg.shared.global [%0], [%1], 16;" :: "r"(dst), "l"(src) : "memory");
}
__device__ __forceinline__ void ldsm4(uint32_t* r, uint32_t addr) {
    asm volatile("ldmatrix.sync.aligned.m8n8.x4.shared.b16 {%0,%1,%2,%3}, [%4];"
                 : "=r"(r[0]), "=r"(r[1]), "=r"(r[2]), "=r"(r[3]) : "r"(addr));
}
__device__ __forceinline__ void mma16816(float* d, const uint32_t* a, const uint32_t* b) {
    asm volatile(
        "mma.sync.aligned.m16n8k16.row.col.f32.f16.f16.f32 "
        "{%0,%1,%2,%3}, {%4,%5,%6,%7}, {%8,%9}, {%0,%1,%2,%3};"
        : "+f"(d[0]), "+f"(d[1]), "+f"(d[2]), "+f"(d[3])
        : "r"(a[0]), "r"(a[1]), "r"(a[2]), "r"(a[3]), "r"(b[0]), "r"(b[1]));
}
__device__ __forceinline__ void hsplit(float v, __half* a, __half* b) {
    __half x = __float2half_rn(v);
    *a = x;
    *b = __float2half_rn(v - __half2float(x));
}
__device__ __forceinline__ unsigned ldacq(unsigned* p) {
    unsigned v;
    asm volatile("ld.acquire.gpu.u32 %0, [%1];" : "=r"(v) : "l"(p) : "memory");
    return v;
}

// ---------------- grid barrier ----------------
__device__ __forceinline__ void gsync() {
    __syncthreads();
    if (threadIdx.x == 0) {
        __threadfence();
        unsigned gen = g_gen;
        if (atomicAdd(&g_cnt, 1u) == NBLK - 1u) {
            g_cnt = 0u;
            __threadfence();
            g_gen = gen + 1u;
        } else {
            while (g_gen == gen) { __nanosleep(32); }
        }
        __threadfence();
    }
    __syncthreads();
}

// ---------------- chunk loader ----------------
__device__ __forceinline__ void load_chunk(
    const __half* __restrict__ W1, const __half* __restrict__ W2, int K,
    const __half* __restrict__ xp1, const __half* __restrict__ xp2, int K1,
    const __half* __restrict__ hp1, const __half* __restrict__ hp2,
    int jbase, int kb, uint32_t su, int buf) {
    int t = threadIdx.x;
#pragma unroll
    for (int pl = 0; pl < 2; pl++) {
        const __half* Wp = pl ? W2 : W1;
#pragma unroll
        for (int i = 0; i < 4; i++) {
            int idx = t + i * 256;
            int row = idx >> 3, seg = idx & 7;
            const __half* src = Wp + (size_t)(jbase + row) * K + kb + seg * 8;
            cp_async16(su + ABUF(buf, pl) + SW(row * 128 + seg * 16), src);
        }
    }
#pragma unroll
    for (int pl = 0; pl < 2; pl++) {
        const __half* xp = pl ? xp2 : xp1;
        const __half* hp = pl ? hp2 : hp1;
#pragma unroll
        for (int i = 0; i < 2; i++) {
            int idx = t + i * 256;
            int row = idx >> 3, seg = idx & 7;
            int k = kb + seg * 8;
            const __half* src = (k < K1) ? xp + (size_t)row * K1 + k
                                         : hp + (size_t)row * HD + (k - K1);
            cp_async16(su + BBUF(buf, pl) + SW(row * 128 + seg * 16), src);
        }
    }
    asm volatile("cp.async.commit_group;" ::: "memory");
}

// ---------------- HMMA GEMM: 128j x 64b tile, fp16 split-2, z -> [j][b] local ----------------
__device__ void tc_gemm(const __half* __restrict__ W1, const __half* __restrict__ W2, int K,
                        const __half* __restrict__ xp1, const __half* __restrict__ xp2, int K1,
                        const __half* __restrict__ hp1, const __half* __restrict__ hp2,
                        int jbase, int kbase, int nchunk,
                        float* __restrict__ zbase, uint32_t su) {
    int t = threadIdx.x, lane = t & 31, w = t >> 5;
    int wm = w & 3, wn = w >> 2;
    int m0 = wm * 32, n0 = wn * 32;

    float acc[2][4][4];
#pragma unroll
    for (int a = 0; a < 2; a++)
#pragma unroll
        for (int b = 0; b < 4; b++)
#pragma unroll
            for (int cc = 0; cc < 4; cc++) acc[a][b][cc] = 0.f;

    load_chunk(W1, W2, K, xp1, xp2, K1, hp1, hp2, jbase, kbase, su, 0);

    for (int c = 0; c < nchunk; c++) {
        int buf = c & 1;
        if (c + 1 < nchunk) {
            load_chunk(W1, W2, K, xp1, xp2, K1, hp1, hp2, jbase, kbase + (c + 1) * 64, su, buf ^ 1);
            asm volatile("cp.async.wait_group 1;" ::: "memory");
        } else {
            asm volatile("cp.async.wait_group 0;" ::: "memory");
        }
        __syncthreads();

        uint32_t a1b = su + ABUF(buf, 0), a2b = su + ABUF(buf, 1);
        uint32_t b1b = su + BBUF(buf, 0), b2b = su + BBUF(buf, 1);
#pragma unroll
        for (int ks = 0; ks < 4; ks++) {
            uint32_t a1[2][4], a2[2][4];
            int arow = m0 + (lane & 15);
            int aseg = ks * 2 + (lane >> 4);
#pragma unroll
            for (int mi = 0; mi < 2; mi++) {
                uint32_t off = SW((arow + mi * 16) * 128 + aseg * 16);
                ldsm4(a1[mi], a1b + off);
                ldsm4(a2[mi], a2b + off);
            }
#pragma unroll
            for (int nb = 0; nb < 2; nb++) {
                int nrow = n0 + nb * 16 + ((lane >> 4) << 3) + (lane & 7);
                int bseg = ks * 2 + ((lane >> 3) & 1);
                uint32_t off = SW(nrow * 128 + bseg * 16);
                uint32_t b1[4], b2[4];
                ldsm4(b1, b1b + off);
                ldsm4(b2, b2b + off);
#pragma unroll
                for (int mi = 0; mi < 2; mi++) {
                    mma16816(acc[mi][nb * 2],     a1[mi], b1);
                    mma16816(acc[mi][nb * 2],     a1[mi], b2);
                    mma16816(acc[mi][nb * 2],     a2[mi], b1);
                    mma16816(acc[mi][nb * 2 + 1], a1[mi], b1 + 2);
                    mma16816(acc[mi][nb * 2 + 1], a1[mi], b2 + 2);
                    mma16816(acc[mi][nb * 2 + 1], a2[mi], b1 + 2);
                }
            }
        }
        __syncthreads();
    }

    // epilogue: z local [j][b]
    int g = lane >> 2, q = lane & 3;
#pragma unroll
    for (int mi = 0; mi < 2; mi++)
#pragma unroll
        for (int nf = 0; nf < 4; nf++) {
            int jl = m0 + mi * 16 + g;
            int b = n0 + nf * 8 + q * 2;
            *(float2*)&zbase[jl * 64 + b]       = make_float2(acc[mi][nf][0], acc[mi][nf][1]);
            *(float2*)&zbase[(jl + 8) * 64 + b] = make_float2(acc[mi][nf][2], acc[mi][nf][3]);
        }
}

// ---------------- the single persistent kernel ----------------
__global__ void __launch_bounds__(NTHR, 2)
seq_main(const int* __restrict__ input_ids, const int* __restrict__ tag_ids,
         const float* __restrict__ enc_embed,
         const float* __restrict__ enc_Wih0, const float* __restrict__ enc_Whh0, const float* __restrict__ enc_b0,
         const float* __restrict__ enc_Wih1, const float* __restrict__ enc_Whh1, const float* __restrict__ enc_b1,
         const float* __restrict__ dec_embed,
         const float* __restrict__ dec_Wih0, const float* __restrict__ dec_Whh0, const float* __restrict__ dec_b0,
         const float* __restrict__ dec_Wih1, const float* __restrict__ dec_Whh1, const float* __restrict__ dec_b1,
         const float* __restrict__ dec_linW, const float* __restrict__ dec_linb,
         float* __restrict__ out, int out_size) {
    extern __shared__ char smem[];
    uint32_t su = smem_u32(smem);
    int bid = blockIdx.x;
    int t = threadIdx.x;
    int gid = bid * NTHR + t;

    // ---- phase 0: gate-interleaved weight plane split + prep ----
    // packed row p <- source row s = (p&3)*1024 + (p>>2)
    for (int p = bid; p < 4096; p += NBLK) {
        int s = (p & 3) * 1024 + (p >> 2);
        for (int k = t; k < 512; k += NTHR) {
            size_t d = (size_t)p * 1536 + k;
            hsplit(enc_Wih0[(size_t)s * 512 + k], &g_e0w1[d], &g_e0w2[d]);
            hsplit(dec_Wih0[(size_t)s * 512 + k], &g_d0w1[d], &g_d0w2[d]);
        }
        for (int k = t; k < 1024; k += NTHR) {
            size_t d0 = (size_t)p * 1536 + 512 + k;
            hsplit(enc_Whh0[(size_t)s * 1024 + k], &g_e0w1[d0], &g_e0w2[d0]);
            hsplit(dec_Whh0[(size_t)s * 1024 + k], &g_d0w1[d0], &g_d0w2[d0]);
            size_t d1 = (size_t)p * 2048 + k;
            hsplit(enc_Wih1[(size_t)s * 1024 + k], &g_e1w1[d1], &g_e1w2[d1]);
            hsplit(dec_Wih1[(size_t)s * 1024 + k], &g_d1w1[d1], &g_d1w2[d1]);
            size_t d2 = d1 + 1024;
            hsplit(enc_Whh1[(size_t)s * 1024 + k], &g_e1w1[d2], &g_e1w2[d2]);
            hsplit(dec_Whh1[(size_t)s * 1024 + k], &g_d1w1[d2], &g_d1w2[d2]);
        }
        if (t == 0) {
            g_be0[p] = enc_b0[s]; g_be1[p] = enc_b1[s];
            g_bd0[p] = dec_b0[s]; g_bd1[p] = dec_b1[s];
        }
    }
    for (int i = gid; i < 1024 * 1024; i += NBLK * NTHR)
        hsplit(dec_linW[i], &g_lnw1[i], &g_lnw2[i]);

    for (int i = gid; i < SRCL * BSZ * ED; i += NBLK * NTHR) {
        int step = i / (BSZ * ED);
        int r = i % (BSZ * ED);
        int b = r / ED, k = r % ED;
        int id = input_ids[b * SRCL + step];
        hsplit(enc_embed[(size_t)id * ED + k], &g_xe1[i], &g_xe2[i]);
    }
    if (bid == 0) {
        for (int i = t; i < BSZ * ED; i += NTHR) {
            int k = i % ED;
            hsplit(dec_embed[k], &g_xd1[i], &g_xd2[i]);
        }
    }
    for (int i = gid; i < BSZ * HD; i += NBLK * NTHR) {
        g_c0f[i] = 0.f; g_c1f[i] = 0.f;
        g_h0p1[i] = __half(0.f); g_h0p2[i] = __half(0.f);
        g_h1p1[i] = __half(0.f); g_h1p2[i] = __half(0.f);
    }
    if (gid < 32) g_jcnt[gid] = 0;   // reset fine-sync counters each launch
    gsync();

    const int jt = bid >> 3, ks = bid & 7;      // cells: 32 j-tiles x 8 k-splits
    const int jtL = bid >> 4, ksL = bid & 15;   // logits: 8 j-tiles x 16 k-splits (bid<128)
    float* zc = g_zpart + (size_t)(jt * 8 + ks) * 8192;
    unsigned cellcnt = 0;

    // fused fine-sync + gates (block handles its jt's 32 units x 8 b-columns)
    const int gu = t >> 3;                 // local unit 0..31
    const int gb = ks * 8 + (t & 7);       // batch column
    const int ug = jt * 32 + gu;           // global unit
    const int cidx = gb * HD + ug;

#define FINE_SYNC() do {                                              \
        cellcnt++;                                                    \
        __syncthreads();                                              \
        if (t == 0) {                                                 \
            __threadfence();                                          \
            atomicAdd(&g_jcnt[jt], 1u);                               \
            unsigned tgt = cellcnt * 8u;                              \
            while (ldacq(&g_jcnt[jt]) < tgt) { }                      \
        }                                                             \
        __syncthreads();                                              \
        __threadfence();                                              \
    } while (0)

#define GATES(BIAS, CARR, HP1, HP2) do {                              \
        const float* zb = g_zpart + (size_t)jt * 8 * 8192;            \
        float zv0 = 0.f, zv1 = 0.f, zv2 = 0.f, zv3 = 0.f;             \
        _Pragma("unroll")                                             \
        for (int s = 0; s < 8; s++) {                                 \
            const float* zs = zb + (size_t)s * 8192 + gu * 256 + gb;  \
            zv0 += zs[0]; zv1 += zs[64]; zv2 += zs[128]; zv3 += zs[192]; \
        }                                                             \
        zv0 += BIAS[jt * 128 + 4 * gu + 0];                           \
        zv1 += BIAS[jt * 128 + 4 * gu + 1];                           \
        zv2 += BIAS[jt * 128 + 4 * gu + 2];                           \
        zv3 += BIAS[jt * 128 + 4 * gu + 3];                           \
        float cn = sigm(zv1) * CARR[cidx] + sigm(zv0) * tanhf(zv2);   \
        CARR[cidx] = cn;                                              \
        float hn = sigm(zv3) * tanhf(cn);                             \
        hsplit(hn, &HP1[cidx], &HP2[cidx]);                           \
    } while (0)

    // -------- encoder --------
    for (int ts = 0; ts < SRCL; ts++) {
        tc_gemm(g_e0w1, g_e0w2, 1536,
                g_xe1 + (size_t)ts * BSZ * ED, g_xe2 + (size_t)ts * BSZ * ED, ED,
                g_h0p1, g_h0p2, jt * 128, ks * 192, 3, zc, su);
        FINE_SYNC();
        GATES(g_be0, g_c0f, g_h0p1, g_h0p2);
        gsync();
        tc_gemm(g_e1w1, g_e1w2, 2048, g_h0p1, g_h0p2, HD, g_h1p1, g_h1p2,
                jt * 128, ks * 256, 4, zc, su);
        FINE_SYNC();
        GATES(g_be1, g_c1f, g_h1p1, g_h1p2);
        gsync();
    }

    // -------- decoder --------
    float* lg = (float*)(smem + OFF_LG);
    float* rv = (float*)(smem + OFF_RV);
    int*   ri = (int*)(smem + OFF_RI);
    float* rs = (float*)(smem + OFF_RS);

    for (int ts = 0; ts < TGTL; ts++) {
        tc_gemm(g_d0w1, g_d0w2, 1536, g_xd1, g_xd2, ED, g_h0p1, g_h0p2,
                jt * 128, ks * 192, 3, zc, su);
        FINE_SYNC();
        GATES(g_bd0, g_c0f, g_h0p1, g_h0p2);
        gsync();
        tc_gemm(g_d1w1, g_d1w2, 2048, g_h0p1, g_h0p2, HD, g_h1p1, g_h1p2,
                jt * 128, ks * 256, 4, zc, su);
        FINE_SYNC();
        GATES(g_bd1, g_c1f, g_h1p1, g_h1p2);
        gsync();
        if (bid < 128) {
            tc_gemm(g_lnw1, g_lnw2, 1024, g_h1p1, g_h1p2, HD, g_h1p1, g_h1p2,
                    jtL * 128, ksL * 64, 1,
                    g_zpart + (size_t)(jtL * 16 + ksL) * 8192, su);
        }
        gsync();

        if (bid < BSZ) {
            int b = bid;
#pragma unroll
            for (int i = 0; i < 4; i++) {
                int u = t + i * 256;
                float s = 0.f;
                const float* zb = g_zpart + (size_t)(u >> 7) * 16 * 8192 + (u & 127) * 64 + b;
#pragma unroll
                for (int sp = 0; sp < 16; sp++) s += zb[(size_t)sp * 8192];
                lg[u] = s + dec_linb[u];
            }
            __syncthreads();
            float mv = lg[t]; int mi = t;
#pragma unroll
            for (int i = 1; i < 4; i++) {
                int u = t + i * 256;
                float v = lg[u];
                if (v > mv) { mv = v; mi = u; }
            }
            rv[t] = mv; ri[t] = mi;
            __syncthreads();
            for (int off = 128; off > 0; off >>= 1) {
                if (t < off) {
                    float vo = rv[t + off]; int io = ri[t + off];
                    if (vo > rv[t] || (vo == rv[t] && io < ri[t])) { rv[t] = vo; ri[t] = io; }
                }
                __syncthreads();
            }
            float m = rv[0];
            float ps = 0.f;
#pragma unroll
            for (int i = 0; i < 4; i++) ps += expf(lg[t + i * 256] - m);
            rs[t] = ps;
            __syncthreads();
            for (int off = 128; off > 0; off >>= 1) {
                if (t < off) rs[t] += rs[t + off];
                __syncthreads();
            }
            float lse = m + logf(rs[0]);
#pragma unroll
            for (int i = 0; i < 4; i++) {
                int u = t + i * 256;
                out[(size_t)ts * (BSZ * HD) + b * HD + u] = lg[u] - lse;
            }
            int mi0 = ri[0];
            for (int k = t; k < ED; k += NTHR)
                hsplit(dec_embed[(size_t)mi0 * ED + k], &g_xd1[b * ED + k], &g_xd2[b * ED + k]);
            if (t == 0) {
                int tg = tag_ids[b * TGTL + ts];
                g_nll[ts * BSZ + b] = (tg != 0) ? (lse - lg[tg]) : 0.0f;
            }
            __syncthreads();
        }
        gsync();
    }

    // -------- loss (block 0) --------
    if (bid == 0) {
        float* stepv = (float*)(smem + OFF_STEPV);
        if (t < TGTL) {
            int cnt = 0;
            float s = 0.f;
            for (int b = 0; b < BSZ; b++) {
                if (tag_ids[b * TGTL + t] != 0) cnt++;
                s += g_nll[t * BSZ + b];
            }
            stepv[t] = s / (float)(cnt > 0 ? cnt : 1);
        }
        __syncthreads();
        if (t == 0) {
            float total = 0.f;
            for (int i = 0; i < TGTL; i++) total += stepv[i];
            if (out_size > OUT_MAIN) out[OUT_MAIN] = total;
        }
    }
}

// ---------------- host launch: ONE graph node ----------------
extern "C" void kernel_launch(void* const* d_in, const int* in_sizes, int n_in,
                              void* d_out, int out_size) {
    cudaFuncSetAttribute(seq_main, cudaFuncAttributeMaxDynamicSharedMemorySize, SMEM_TOTAL);
    seq_main<<<NBLK, NTHR, SMEM_TOTAL>>>(
        (const int*)d_in[0], (const int*)d_in[1], (const float*)d_in[2],
        (const float*)d_in[3], (const float*)d_in[4], (const float*)d_in[5],
        (const float*)d_in[6], (const float*)d_in[7], (const float*)d_in[8],
        (const float*)d_in[9],
        (const float*)d_in[10], (const float*)d_in[11], (const float*)d_in[12],
        (const float*)d_in[13], (const float*)d_in[14], (const float*)d_in[15],
        (const float*)d_in[16], (const float*)d_in[17],
        (float*)d_out, out_size);
}

// round 10
// speedup vs baseline: 1.0662x; 1.0662x over previous
#include <cuda_runtime.h>
#include <cuda_fp16.h>
#include <math.h>
#include <stdint.h>

// ---------------- problem constants ----------------
#define BSZ   64
#define HD    1024
#define ED    512
#define SRCL  128
#define TGTL  128
#define NBLK  128
#define NTHR  256
#define OUT_MAIN (TGTL*BSZ*HD)

// ---------------- SMEM layout: 3-stage pipeline buffers ----------------
#define ABUF(buf,pl) ((buf)*49152 + (pl)*16384)          // [128j][64k] fp16 SW128
#define BBUF(buf,pl) ((buf)*49152 + 32768 + (pl)*8192)   // [64b][64k] fp16 SW128
#define OFF_LG     147456
#define OFF_RV     (OFF_LG + 4096)
#define OFF_RI     (OFF_RV + 1024)
#define OFF_RS     (OFF_RI + 1024)
#define OFF_STEPV  (OFF_RS + 1024)
#define SMEM_TOTAL (OFF_STEPV + 512 + 128)   // ~152KB -> 1 block/SM

#define SW(o) ((o) ^ (((o) >> 3) & 0x70))

// ---------------- device scratch (static, no allocs) ----------------
__device__ __half g_e0w1[4096*1536], g_e0w2[4096*1536];   // gate-interleaved rows
__device__ __half g_e1w1[4096*2048], g_e1w2[4096*2048];
__device__ __half g_d0w1[4096*1536], g_d0w2[4096*1536];
__device__ __half g_d1w1[4096*2048], g_d1w2[4096*2048];
__device__ __half g_lnw1[1024*1024], g_lnw2[1024*1024];   // identity rows
__device__ float  g_be0[4096], g_be1[4096], g_bd0[4096], g_bd1[4096];
__device__ __half g_xe1[SRCL*BSZ*ED], g_xe2[SRCL*BSZ*ED];
__device__ __half g_xd1[BSZ*ED], g_xd2[BSZ*ED];
__device__ __half g_h0p1[BSZ*HD], g_h0p2[BSZ*HD];
__device__ __half g_h1p1[BSZ*HD], g_h1p2[BSZ*HD];
__device__ float  g_c0f[BSZ*HD], g_c1f[BSZ*HD];
__device__ float  g_zpart[1048576];     // cells: [jt32][ks4][128][64]; logits: [jt8][ks16][128][64]
__device__ float  g_nll[TGTL*BSZ];
__device__ volatile unsigned g_barr[NBLK*8];   // padded grid-barrier slots (32B apart)
__device__ volatile unsigned g_jbarr[NBLK*8];  // padded fine-sync slots
__device__ unsigned g_cnt;                     // bootstrap atomic barrier
__device__ volatile unsigned g_gen;

// ---------------- helpers ----------------
__device__ __forceinline__ float sigm(float x) { return 1.0f / (1.0f + expf(-x)); }
__device__ __forceinline__ uint32_t smem_u32(const void* p) {
    uint32_t a;
    asm("{ .reg .u64 t; cvta.to.shared.u64 t, %1; cvt.u32.u64 %0, t; }" : "=r"(a) : "l"(p));
    return a;
}
__device__ __forceinline__ void cp_async16(uint32_t dst, const void* src) {
    asm volatile("cp.async.cg.shared.global [%0], [%1], 16;" :: "r"(dst), "l"(src) : "memory");
}
__device__ __forceinline__ void ldsm4(uint32_t* r, uint32_t addr) {
    asm volatile("ldmatrix.sync.aligned.m8n8.x4.shared.b16 {%0,%1,%2,%3}, [%4];"
                 : "=r"(r[0]), "=r"(r[1]), "=r"(r[2]), "=r"(r[3]) : "r"(addr));
}
__device__ __forceinline__ void mma16816(float* d, const uint32_t* a, const uint32_t* b) {
    asm volatile(
        "mma.sync.aligned.m16n8k16.row.col.f32.f16.f16.f32 "
        "{%0,%1,%2,%3}, {%4,%5,%6,%7}, {%8,%9}, {%0,%1,%2,%3};"
        : "+f"(d[0]), "+f"(d[1]), "+f"(d[2]), "+f"(d[3])
        : "r"(a[0]), "r"(a[1]), "r"(a[2]), "r"(a[3]), "r"(b[0]), "r"(b[1]));
}
__device__ __forceinline__ void hsplit(float v, __half* a, __half* b) {
    __half x = __float2half_rn(v);
    *a = x;
    *b = __float2half_rn(v - __half2float(x));
}

// ---------------- bootstrap atomic barrier (used once, replay-safe) ----------------
__device__ __forceinline__ void gsync_boot() {
    __syncthreads();
    if (threadIdx.x == 0) {
        __threadfence();
        unsigned gen = g_gen;
        if (atomicAdd(&g_cnt, 1u) == NBLK - 1u) {
            g_cnt = 0u;
            __threadfence();
            g_gen = gen + 1u;
        } else {
            while (g_gen == gen) { __nanosleep(32); }
        }
        __threadfence();
    }
    __syncthreads();
}

// ---------------- chunk loader ----------------
__device__ __forceinline__ void load_chunk(
    const __half* __restrict__ W1, const __half* __restrict__ W2, int K,
    const __half* __restrict__ xp1, const __half* __restrict__ xp2, int K1,
    const __half* __restrict__ hp1, const __half* __restrict__ hp2,
    int jbase, int kb, uint32_t su, int buf) {
    int t = threadIdx.x;
#pragma unroll
    for (int pl = 0; pl < 2; pl++) {
        const __half* Wp = pl ? W2 : W1;
#pragma unroll
        for (int i = 0; i < 4; i++) {
            int idx = t + i * 256;
            int row = idx >> 3, seg = idx & 7;
            const __half* src = Wp + (size_t)(jbase + row) * K + kb + seg * 8;
            cp_async16(su + ABUF(buf, pl) + SW(row * 128 + seg * 16), src);
        }
    }
#pragma unroll
    for (int pl = 0; pl < 2; pl++) {
        const __half* xp = pl ? xp2 : xp1;
        const __half* hp = pl ? hp2 : hp1;
#pragma unroll
        for (int i = 0; i < 2; i++) {
            int idx = t + i * 256;
            int row = idx >> 3, seg = idx & 7;
            int k = kb + seg * 8;
            const __half* src = (k < K1) ? xp + (size_t)row * K1 + k
                                         : hp + (size_t)row * HD + (k - K1);
            cp_async16(su + BBUF(buf, pl) + SW(row * 128 + seg * 16), src);
        }
    }
    asm volatile("cp.async.commit_group;" ::: "memory");
}

// ---------------- HMMA GEMM: 128j x 64b tile, fp16 split-2, 3-stage pipeline ----------------
__device__ void tc_gemm(const __half* __restrict__ W1, const __half* __restrict__ W2, int K,
                        const __half* __restrict__ xp1, const __half* __restrict__ xp2, int K1,
                        const __half* __restrict__ hp1, const __half* __restrict__ hp2,
                        int jbase, int kbase, int nchunk,
                        float* __restrict__ zbase, uint32_t su) {
    int t = threadIdx.x, lane = t & 31, w = t >> 5;
    int wm = w & 3, wn = w >> 2;
    int m0 = wm * 32, n0 = wn * 32;

    float acc[2][4][4];
#pragma unroll
    for (int a = 0; a < 2; a++)
#pragma unroll
        for (int b = 0; b < 4; b++)
#pragma unroll
            for (int cc = 0; cc < 4; cc++) acc[a][b][cc] = 0.f;

    load_chunk(W1, W2, K, xp1, xp2, K1, hp1, hp2, jbase, kbase, su, 0);
    if (nchunk > 1)
        load_chunk(W1, W2, K, xp1, xp2, K1, hp1, hp2, jbase, kbase + 64, su, 1);

    for (int c = 0; c < nchunk; c++) {
        int buf = c % 3;
        if (c + 1 < nchunk) asm volatile("cp.async.wait_group 1;" ::: "memory");
        else                asm volatile("cp.async.wait_group 0;" ::: "memory");
        __syncthreads();   // chunk c ready; all warps done reading chunk c-1's buffer
        if (c + 2 < nchunk)
            load_chunk(W1, W2, K, xp1, xp2, K1, hp1, hp2, jbase,
                       kbase + (c + 2) * 64, su, (c + 2) % 3);

        uint32_t a1b = su + ABUF(buf, 0), a2b = su + ABUF(buf, 1);
        uint32_t b1b = su + BBUF(buf, 0), b2b = su + BBUF(buf, 1);
#pragma unroll
        for (int ks = 0; ks < 4; ks++) {
            uint32_t a1[2][4], a2[2][4];
            int arow = m0 + (lane & 15);
            int aseg = ks * 2 + (lane >> 4);
#pragma unroll
            for (int mi = 0; mi < 2; mi++) {
                uint32_t off = SW((arow + mi * 16) * 128 + aseg * 16);
                ldsm4(a1[mi], a1b + off);
                ldsm4(a2[mi], a2b + off);
            }
#pragma unroll
            for (int nb = 0; nb < 2; nb++) {
                int nrow = n0 + nb * 16 + ((lane >> 4) << 3) + (lane & 7);
                int bseg = ks * 2 + ((lane >> 3) & 1);
                uint32_t off = SW(nrow * 128 + bseg * 16);
                uint32_t b1[4], b2[4];
                ldsm4(b1, b1b + off);
                ldsm4(b2, b2b + off);
#pragma unroll
                for (int mi = 0; mi < 2; mi++) {
                    mma16816(acc[mi][nb * 2],     a1[mi], b1);
                    mma16816(acc[mi][nb * 2],     a1[mi], b2);
                    mma16816(acc[mi][nb * 2],     a2[mi], b1);
                    mma16816(acc[mi][nb * 2 + 1], a1[mi], b1 + 2);
                    mma16816(acc[mi][nb * 2 + 1], a1[mi], b2 + 2);
                    mma16816(acc[mi][nb * 2 + 1], a2[mi], b1 + 2);
                }
            }
        }
    }

    // epilogue: z local [j][b]
    int g = lane >> 2, q = lane & 3;
#pragma unroll
    for (int mi = 0; mi < 2; mi++)
#pragma unroll
        for (int nf = 0; nf < 4; nf++) {
            int jl = m0 + mi * 16 + g;
            int b = n0 + nf * 8 + q * 2;
            *(float2*)&zbase[jl * 64 + b]       = make_float2(acc[mi][nf][0], acc[mi][nf][1]);
            *(float2*)&zbase[(jl + 8) * 64 + b] = make_float2(acc[mi][nf][2], acc[mi][nf][3]);
        }
}

// ---------------- the single persistent kernel ----------------
__global__ void __launch_bounds__(NTHR, 1)
seq_main(const int* __restrict__ input_ids, const int* __restrict__ tag_ids,
         const float* __restrict__ enc_embed,
         const float* __restrict__ enc_Wih0, const float* __restrict__ enc_Whh0, const float* __restrict__ enc_b0,
         const float* __restrict__ enc_Wih1, const float* __restrict__ enc_Whh1, const float* __restrict__ enc_b1,
         const float* __restrict__ dec_embed,
         const float* __restrict__ dec_Wih0, const float* __restrict__ dec_Whh0, const float* __restrict__ dec_b0,
         const float* __restrict__ dec_Wih1, const float* __restrict__ dec_Whh1, const float* __restrict__ dec_b1,
         const float* __restrict__ dec_linW, const float* __restrict__ dec_linb,
         float* __restrict__ out, int out_size) {
    extern __shared__ char smem[];
    uint32_t su = smem_u32(smem);
    int bid = blockIdx.x;
    int t = threadIdx.x;
    int gid = bid * NTHR + t;

    const int jt = bid >> 2, ks = bid & 3;      // cells: 32 j-tiles x 4 k-splits
    const int jtL = bid >> 4, ksL = bid & 15;   // logits: 8 j-tiles x 16 k-splits

    // ---- phase 0: gate-interleaved weight plane split + prep ----
    // packed row p <- source row s = (p&3)*1024 + (p>>2)
    for (int p = bid; p < 4096; p += NBLK) {
        int s = (p & 3) * 1024 + (p >> 2);
        for (int k = t; k < 512; k += NTHR) {
            size_t d = (size_t)p * 1536 + k;
            hsplit(enc_Wih0[(size_t)s * 512 + k], &g_e0w1[d], &g_e0w2[d]);
            hsplit(dec_Wih0[(size_t)s * 512 + k], &g_d0w1[d], &g_d0w2[d]);
        }
        for (int k = t; k < 1024; k += NTHR) {
            size_t d0 = (size_t)p * 1536 + 512 + k;
            hsplit(enc_Whh0[(size_t)s * 1024 + k], &g_e0w1[d0], &g_e0w2[d0]);
            hsplit(dec_Whh0[(size_t)s * 1024 + k], &g_d0w1[d0], &g_d0w2[d0]);
            size_t d1 = (size_t)p * 2048 + k;
            hsplit(enc_Wih1[(size_t)s * 1024 + k], &g_e1w1[d1], &g_e1w2[d1]);
            hsplit(dec_Wih1[(size_t)s * 1024 + k], &g_d1w1[d1], &g_d1w2[d1]);
            size_t d2 = d1 + 1024;
            hsplit(enc_Whh1[(size_t)s * 1024 + k], &g_e1w1[d2], &g_e1w2[d2]);
            hsplit(dec_Whh1[(size_t)s * 1024 + k], &g_d1w1[d2], &g_d1w2[d2]);
        }
        if (t == 0) {
            g_be0[p] = enc_b0[s]; g_be1[p] = enc_b1[s];
            g_bd0[p] = dec_b0[s]; g_bd1[p] = dec_b1[s];
        }
    }
    for (int i = gid; i < 1024 * 1024; i += NBLK * NTHR)
        hsplit(dec_linW[i], &g_lnw1[i], &g_lnw2[i]);

    for (int i = gid; i < SRCL * BSZ * ED; i += NBLK * NTHR) {
        int step = i / (BSZ * ED);
        int r = i % (BSZ * ED);
        int b = r / ED, k = r % ED;
        int id = input_ids[b * SRCL + step];
        hsplit(enc_embed[(size_t)id * ED + k], &g_xe1[i], &g_xe2[i]);
    }
    if (bid == 0) {
        for (int i = t; i < BSZ * ED; i += NTHR) {
            int k = i % ED;
            hsplit(dec_embed[k], &g_xd1[i], &g_xd2[i]);
        }
    }
    for (int i = gid; i < BSZ * HD; i += NBLK * NTHR) {
        g_c0f[i] = 0.f; g_c1f[i] = 0.f;
        g_h0p1[i] = __half(0.f); g_h0p2[i] = __half(0.f);
        g_h1p1[i] = __half(0.f); g_h1p2[i] = __half(0.f);
    }
    if (t == 0) {                       // reset distributed-barrier slots each launch
        g_barr[bid * 8] = 0u;
        g_jbarr[bid * 8] = 0u;
    }
    gsync_boot();                       // replay-safe crossing: resets visible everywhere

    unsigned gep = 1, fep = 1;
    float* zc = g_zpart + (size_t)(jt * 4 + ks) * 8192;

#define GSYNC() do {                                                  \
        __syncthreads(); __threadfence();                             \
        if (t == 0) g_barr[bid * 8] = gep;                            \
        if (t < NBLK) { while (g_barr[t * 8] < gep) { } }             \
        __threadfence(); __syncthreads(); gep++;                      \
    } while (0)

#define FINE_SYNC() do {                                              \
        __syncthreads(); __threadfence();                             \
        if (t == 0) g_jbarr[bid * 8] = fep;                           \
        if (t < 4) { while (g_jbarr[(jt * 4 + t) * 8] < fep) { } }    \
        __threadfence(); __syncthreads(); fep++;                      \
    } while (0)

#define GATES(BIAS, CARR, HP1, HP2) do {                              \
        const float* zb = g_zpart + (size_t)jt * 4 * 8192;            \
        _Pragma("unroll")                                             \
        for (int r = 0; r < 2; r++) {                                 \
            int u = (t >> 4) + r * 16;                                \
            int bcol = ks * 16 + (t & 15);                            \
            float zv0 = 0.f, zv1 = 0.f, zv2 = 0.f, zv3 = 0.f;         \
            _Pragma("unroll")                                         \
            for (int s2 = 0; s2 < 4; s2++) {                          \
                const float* zs = zb + (size_t)s2 * 8192 + u * 256 + bcol; \
                zv0 += zs[0]; zv1 += zs[64]; zv2 += zs[128]; zv3 += zs[192]; \
            }                                                         \
            zv0 += BIAS[jt * 128 + 4 * u + 0];                        \
            zv1 += BIAS[jt * 128 + 4 * u + 1];                        \
            zv2 += BIAS[jt * 128 + 4 * u + 2];                        \
            zv3 += BIAS[jt * 128 + 4 * u + 3];                        \
            int ci = bcol * HD + jt * 32 + u;                         \
            float cn = sigm(zv1) * CARR[ci] + sigm(zv0) * tanhf(zv2); \
            CARR[ci] = cn;                                            \
            float hn = sigm(zv3) * tanhf(cn);                         \
            hsplit(hn, &HP1[ci], &HP2[ci]);                           \
        }                                                             \
    } while (0)

    // -------- encoder --------
    for (int ts = 0; ts < SRCL; ts++) {
        tc_gemm(g_e0w1, g_e0w2, 1536,
                g_xe1 + (size_t)ts * BSZ * ED, g_xe2 + (size_t)ts * BSZ * ED, ED,
                g_h0p1, g_h0p2, jt * 128, ks * 384, 6, zc, su);
        FINE_SYNC();
        GATES(g_be0, g_c0f, g_h0p1, g_h0p2);
        GSYNC();
        tc_gemm(g_e1w1, g_e1w2, 2048, g_h0p1, g_h0p2, HD, g_h1p1, g_h1p2,
                jt * 128, ks * 512, 8, zc, su);
        FINE_SYNC();
        GATES(g_be1, g_c1f, g_h1p1, g_h1p2);
        GSYNC();
    }

    // -------- decoder --------
    float* lg = (float*)(smem + OFF_LG);
    float* rv = (float*)(smem + OFF_RV);
    int*   ri = (int*)(smem + OFF_RI);
    float* rs = (float*)(smem + OFF_RS);

    for (int ts = 0; ts < TGTL; ts++) {
        tc_gemm(g_d0w1, g_d0w2, 1536, g_xd1, g_xd2, ED, g_h0p1, g_h0p2,
                jt * 128, ks * 384, 6, zc, su);
        FINE_SYNC();
        GATES(g_bd0, g_c0f, g_h0p1, g_h0p2);
        GSYNC();
        tc_gemm(g_d1w1, g_d1w2, 2048, g_h0p1, g_h0p2, HD, g_h1p1, g_h1p2,
                jt * 128, ks * 512, 8, zc, su);
        FINE_SYNC();
        GATES(g_bd1, g_c1f, g_h1p1, g_h1p2);
        GSYNC();
        tc_gemm(g_lnw1, g_lnw2, 1024, g_h1p1, g_h1p2, HD, g_h1p1, g_h1p2,
                jtL * 128, ksL * 64, 1,
                g_zpart + (size_t)(jtL * 16 + ksL) * 8192, su);
        GSYNC();

        if (bid < BSZ) {
            int b = bid;
#pragma unroll
            for (int i = 0; i < 4; i++) {
                int u = t + i * 256;
                float s = 0.f;
                const float* zb = g_zpart + (size_t)(u >> 7) * 16 * 8192 + (u & 127) * 64 + b;
#pragma unroll
                for (int sp = 0; sp < 16; sp++) s += zb[(size_t)sp * 8192];
                lg[u] = s + dec_linb[u];
            }
            __syncthreads();
            float mv = lg[t]; int mi = t;
#pragma unroll
            for (int i = 1; i < 4; i++) {
                int u = t + i * 256;
                float v = lg[u];
                if (v > mv) { mv = v; mi = u; }
            }
            rv[t] = mv; ri[t] = mi;
            __syncthreads();
            for (int off = 128; off > 0; off >>= 1) {
                if (t < off) {
                    float vo = rv[t + off]; int io = ri[t + off];
                    if (vo > rv[t] || (vo == rv[t] && io < ri[t])) { rv[t] = vo; ri[t] = io; }
                }
                __syncthreads();
            }
            float m = rv[0];
            float ps = 0.f;
#pragma unroll
            for (int i = 0; i < 4; i++) ps += expf(lg[t + i * 256] - m);
            rs[t] = ps;
            __syncthreads();
            for (int off = 128; off > 0; off >>= 1) {
                if (t < off) rs[t] += rs[t + off];
                __syncthreads();
            }
            float lse = m + logf(rs[0]);
#pragma unroll
            for (int i = 0; i < 4; i++) {
                int u = t + i * 256;
                out[(size_t)ts * (BSZ * HD) + b * HD + u] = lg[u] - lse;
            }
            int mi0 = ri[0];
            for (int k = t; k < ED; k += NTHR)
                hsplit(dec_embed[(size_t)mi0 * ED + k], &g_xd1[b * ED + k], &g_xd2[b * ED + k]);
            if (t == 0) {
                int tg = tag_ids[b * TGTL + ts];
                g_nll[ts * BSZ + b] = (tg != 0) ? (lse - lg[tg]) : 0.0f;
            }
            __syncthreads();
        }
        GSYNC();
    }

    // -------- loss (block 0) --------
    if (bid == 0) {
        float* stepv = (float*)(smem + OFF_STEPV);
        if (t < TGTL) {
            int cnt = 0;
            float s = 0.f;
            for (int b = 0; b < BSZ; b++) {
                if (tag_ids[b * TGTL + t] != 0) cnt++;
                s += g_nll[t * BSZ + b];
            }
            stepv[t] = s / (float)(cnt > 0 ? cnt : 1);
        }
        __syncthreads();
        if (t == 0) {
            float total = 0.f;
            for (int i = 0; i < TGTL; i++) total += stepv[i];
            if (out_size > OUT_MAIN) out[OUT_MAIN] = total;
        }
    }
}

// ---------------- host launch: ONE graph node ----------------
extern "C" void kernel_launch(void* const* d_in, const int* in_sizes, int n_in,
                              void* d_out, int out_size) {
    cudaFuncSetAttribute(seq_main, cudaFuncAttributeMaxDynamicSharedMemorySize, SMEM_TOTAL);
    seq_main<<<NBLK, NTHR, SMEM_TOTAL>>>(
        (const int*)d_in[0], (const int*)d_in[1], (const float*)d_in[2],
        (const float*)d_in[3], (const float*)d_in[4], (const float*)d_in[5],
        (const float*)d_in[6], (const float*)d_in[7], (const float*)d_in[8],
        (const float*)d_in[9],
        (const float*)d_in[10], (const float*)d_in[11], (const float*)d_in[12],
        (const float*)d_in[13], (const float*)d_in[14], (const float*)d_in[15],
        (const float*)d_in[16], (const float*)d_in[17],
        (float*)d_out, out_size);
}

// round 16
// speedup vs baseline: 1.2672x; 1.1885x over previous
#include <cuda_runtime.h>
#include <cuda_fp16.h>
#include <math.h>
#include <stdint.h>

// ---------------- problem constants ----------------
#define BSZ   64
#define HD    1024
#define ED    512
#define SRCL  128
#define TGTL  128
#define NJ4   4096
#define NBLK  128
#define NTHR  512
#define OUT_MAIN (TGTL*BSZ*HD)

// ---------------- SMEM layout: double-buffered chunks ----------------
#define ABUF(buf,pl) ((buf)*49152 + (pl)*16384)          // [128j][64k] fp16 SW128
#define BBUF(buf,pl) ((buf)*49152 + 32768 + (pl)*8192)   // [64b][64k] fp16 SW128
#define OFF_LG     98304
#define OFF_RV     (OFF_LG + 4096)
#define OFF_RI     (OFF_RV + 2048)
#define OFF_RS     (OFF_RI + 2048)
#define OFF_STEPV  (OFF_RS + 2048)
#define SMEM_TOTAL (OFF_STEPV + 512 + 128)

#define SW(o) ((o) ^ (((o) >> 3) & 0x70))

// ---------------- device scratch (static, no allocs) ----------------
__device__ __half g_e0w1[4096*1536], g_e0w2[4096*1536];
__device__ __half g_e1w1[4096*2048], g_e1w2[4096*2048];
__device__ __half g_d0w1[4096*1536], g_d0w2[4096*1536];
__device__ __half g_d1w1[4096*2048], g_d1w2[4096*2048];
__device__ __half g_lnw1[1024*1024], g_lnw2[1024*1024];
__device__ __half g_xe1[SRCL*BSZ*ED], g_xe2[SRCL*BSZ*ED];
__device__ __half g_xd1[BSZ*ED], g_xd2[BSZ*ED];
__device__ __half g_h0p1[BSZ*HD], g_h0p2[BSZ*HD];
__device__ __half g_h1p1[BSZ*HD], g_h1p2[BSZ*HD];
__device__ float  g_c0f[BSZ*HD], g_c1f[BSZ*HD];
__device__ float  g_zpart[1048576];
__device__ float  g_nll[TGTL*BSZ];
__device__ unsigned g_cnt;
__device__ volatile unsigned g_gen;

// ---------------- helpers ----------------
__device__ __forceinline__ float sigm(float x) { return 1.0f / (1.0f + expf(-x)); }
__device__ __forceinline__ uint32_t smem_u32(const void* p) {
    uint32_t a;
    asm("{ .reg .u64 t; cvta.to.shared.u64 t, %1; cvt.u32.u64 %0, t; }" : "=r"(a) : "l"(p));
    return a;
}
__device__ __forceinline__ void cp_async16(uint32_t dst, const void* src) {
    asm volatile("cp.async.cg.shared.global [%0], [%1], 16;" :: "r"(dst), "l"(src) : "memory");
}
__device__ __forceinline__ void ldsm4(uint32_t* r, uint32_t addr) {
    asm volatile("ldmatrix.sync.aligned.m8n8.x4.shared.b16 {%0,%1,%2,%3}, [%4];"
                 : "=r"(r[0]), "=r"(r[1]), "=r"(r[2]), "=r"(r[3]) : "r"(addr));
}
__device__ __forceinline__ void mma16816(float* d, const uint32_t* a, const uint32_t* b) {
    asm volatile(
        "mma.sync.aligned.m16n8k16.row.col.f32.f16.f16.f32 "
        "{%0,%1,%2,%3}, {%4,%5,%6,%7}, {%8,%9}, {%0,%1,%2,%3};"
        : "+f"(d[0]), "+f"(d[1]), "+f"(d[2]), "+f"(d[3])
        : "r"(a[0]), "r"(a[1]), "r"(a[2]), "r"(a[3]), "r"(b[0]), "r"(b[1]));
}
__device__ __forceinline__ void hsplit(float v, __half* a, __half* b) {
    __half x = __float2half_rn(v);
    *a = x;
    *b = __float2half_rn(v - __half2float(x));
}

// ---------------- central atomic grid barrier (R5-proven) ----------------
__device__ __forceinline__ void gsync() {
    __syncthreads();
    if (threadIdx.x == 0) {
        __threadfence();
        unsigned gen = g_gen;
        if (atomicAdd(&g_cnt, 1u) == NBLK - 1u) {
            g_cnt = 0u;
            __threadfence();
            g_gen = gen + 1u;
        } else {
            while (g_gen == gen) { __nanosleep(64); }
        }
        __threadfence();
    }
    __syncthreads();
}

// ---------------- chunk loader (512 threads) ----------------
__device__ __forceinline__ void load_chunk(
    const __half* __restrict__ W1, const __half* __restrict__ W2, int K,
    const __half* __restrict__ xp1, const __half* __restrict__ xp2, int K1,
    const __half* __restrict__ hp1, const __half* __restrict__ hp2,
    int jbase, int kb, uint32_t su, int buf) {
    int t = threadIdx.x;
#pragma unroll
    for (int pl = 0; pl < 2; pl++) {
        const __half* Wp = pl ? W2 : W1;
#pragma unroll
        for (int i = 0; i < 2; i++) {
            int idx = t + i * 512;        // 1024 float4 per A plane
            int row = idx >> 3, seg = idx & 7;
            const __half* src = Wp + (size_t)(jbase + row) * K + kb + seg * 8;
            cp_async16(su + ABUF(buf, pl) + SW(row * 128 + seg * 16), src);
        }
    }
#pragma unroll
    for (int pl = 0; pl < 2; pl++) {
        const __half* xp = pl ? xp2 : xp1;
        const __half* hp = pl ? hp2 : hp1;
        {
            int row = t >> 3, seg = t & 7;  // 512 float4 per B plane
            int k = kb + seg * 8;
            const __half* src = (k < K1) ? xp + (size_t)row * K1 + k
                                         : hp + (size_t)row * HD + (k - K1);
            cp_async16(su + BBUF(buf, pl) + SW(row * 128 + seg * 16), src);
        }
    }
    asm volatile("cp.async.commit_group;" ::: "memory");
}

// ---------------- HMMA GEMM: 128j x 64b tile, 16 warps (warp tile 32x16) ----------------
__device__ void tc_gemm(const __half* __restrict__ W1, const __half* __restrict__ W2, int K,
                        const __half* __restrict__ xp1, const __half* __restrict__ xp2, int K1,
                        const __half* __restrict__ hp1, const __half* __restrict__ hp2,
                        int jbase, int kbase, int nchunk, int NJ,
                        float* __restrict__ zout, uint32_t su) {
    int t = threadIdx.x, lane = t & 31, w = t >> 5;
    int wm = w & 3, wn = w >> 2;          // 4 x 4 warp grid
    int m0 = wm * 32, n0 = wn * 16;

    float acc[2][2][4];                    // [mi][n-half][frag]
#pragma unroll
    for (int a = 0; a < 2; a++)
#pragma unroll
        for (int b = 0; b < 2; b++)
#pragma unroll
            for (int cc = 0; cc < 4; cc++) acc[a][b][cc] = 0.f;

    load_chunk(W1, W2, K, xp1, xp2, K1, hp1, hp2, jbase, kbase, su, 0);

    for (int c = 0; c < nchunk; c++) {
        int buf = c & 1;
        if (c + 1 < nchunk) {
            load_chunk(W1, W2, K, xp1, xp2, K1, hp1, hp2, jbase, kbase + (c + 1) * 64, su, buf ^ 1);
            asm volatile("cp.async.wait_group 1;" ::: "memory");
        } else {
            asm volatile("cp.async.wait_group 0;" ::: "memory");
        }
        __syncthreads();

        uint32_t a1b = su + ABUF(buf, 0), a2b = su + ABUF(buf, 1);
        uint32_t b1b = su + BBUF(buf, 0), b2b = su + BBUF(buf, 1);
#pragma unroll
        for (int ks = 0; ks < 4; ks++) {
            uint32_t a1[2][4], a2[2][4];
            int arow = m0 + (lane & 15);
            int aseg = ks * 2 + (lane >> 4);
#pragma unroll
            for (int mi = 0; mi < 2; mi++) {
                uint32_t off = SW((arow + mi * 16) * 128 + aseg * 16);
                ldsm4(a1[mi], a1b + off);
                ldsm4(a2[mi], a2b + off);
            }
            // B frag: 16 rows (n0..n0+15), one ldsm4 per plane
            int nrow = n0 + ((lane >> 4) << 3) + (lane & 7);
            int bseg = ks * 2 + ((lane >> 3) & 1);
            uint32_t boff = SW(nrow * 128 + bseg * 16);
            uint32_t b1[4], b2[4];
            ldsm4(b1, b1b + boff);
            ldsm4(b2, b2b + boff);
            // pass-major order: per-accumulator sequence a1b1, a1b2, a2b1 (bit-identical)
            mma16816(acc[0][0], a1[0], b1);
            mma16816(acc[1][0], a1[1], b1);
            mma16816(acc[0][1], a1[0], b1 + 2);
            mma16816(acc[1][1], a1[1], b1 + 2);
            mma16816(acc[0][0], a1[0], b2);
            mma16816(acc[1][0], a1[1], b2);
            mma16816(acc[0][1], a1[0], b2 + 2);
            mma16816(acc[1][1], a1[1], b2 + 2);
            mma16816(acc[0][0], a2[0], b1);
            mma16816(acc[1][0], a2[1], b1);
            mma16816(acc[0][1], a2[0], b1 + 2);
            mma16816(acc[1][1], a2[1], b1 + 2);
        }
        __syncthreads();
    }

    // epilogue: z[b][j] global layout
    int g = lane >> 2, q = lane & 3;
#pragma unroll
    for (int mi = 0; mi < 2; mi++)
#pragma unroll
        for (int half = 0; half < 2; half++) {
            int j = jbase + m0 + mi * 16 + g;
            int b = n0 + half * 8 + q * 2;
            zout[(size_t)b * NJ + j]           = acc[mi][half][0];
            zout[(size_t)(b + 1) * NJ + j]     = acc[mi][half][1];
            zout[(size_t)b * NJ + j + 8]       = acc[mi][half][2];
            zout[(size_t)(b + 1) * NJ + j + 8] = acc[mi][half][3];
        }
}

// ---------------- LSTM gates: reduce 4 k-splits, emit h plane pair ----------------
__device__ void gates_phase(const float* __restrict__ zpart, const float* __restrict__ bias,
                            float* __restrict__ c, __half* __restrict__ hp1,
                            __half* __restrict__ hp2, int bid) {
    int idx = bid * NTHR + threadIdx.x;    // 0..65535 exactly
    int b = idx >> 10, u = idx & 1023;
    float zi = 0.f, zf = 0.f, zg = 0.f, zo = 0.f;
#pragma unroll
    for (int s = 0; s < 4; s++) {
        const float* base = zpart + ((size_t)s * 64 + b) * NJ4;
        zi += base[u]; zf += base[1024 + u];
        zg += base[2048 + u]; zo += base[3072 + u];
    }
    zi += bias[u]; zf += bias[1024 + u]; zg += bias[2048 + u]; zo += bias[3072 + u];
    float cn = sigm(zf) * c[idx] + sigm(zi) * tanhf(zg);
    c[idx] = cn;
    float hn = sigm(zo) * tanhf(cn);
    hsplit(hn, &hp1[idx], &hp2[idx]);
}

// ---------------- the single persistent kernel ----------------
__global__ void __launch_bounds__(NTHR, 1)
seq_main(const int* __restrict__ input_ids, const int* __restrict__ tag_ids,
         const float* __restrict__ enc_embed,
         const float* __restrict__ enc_Wih0, const float* __restrict__ enc_Whh0, const float* __restrict__ enc_b0,
         const float* __restrict__ enc_Wih1, const float* __restrict__ enc_Whh1, const float* __restrict__ enc_b1,
         const float* __restrict__ dec_embed,
         const float* __restrict__ dec_Wih0, const float* __restrict__ dec_Whh0, const float* __restrict__ dec_b0,
         const float* __restrict__ dec_Wih1, const float* __restrict__ dec_Whh1, const float* __restrict__ dec_b1,
         const float* __restrict__ dec_linW, const float* __restrict__ dec_linb,
         float* __restrict__ out, int out_size) {
    extern __shared__ char smem[];
    uint32_t su = smem_u32(smem);
    int bid = blockIdx.x;
    int t = threadIdx.x;
    int gid = bid * NTHR + t;

    // ---- phase 0: weight plane splits (K-concat layout), embed prep, state init ----
    for (int i = gid; i < 4096 * 512; i += NBLK * NTHR) {
        int r = i >> 9, k = i & 511;
        hsplit(enc_Wih0[i], &g_e0w1[(size_t)r * 1536 + k], &g_e0w2[(size_t)r * 1536 + k]);
        hsplit(dec_Wih0[i], &g_d0w1[(size_t)r * 1536 + k], &g_d0w2[(size_t)r * 1536 + k]);
    }
    for (int i = gid; i < 4096 * 1024; i += NBLK * NTHR) {
        int r = i >> 10, k = i & 1023;
        size_t o0 = (size_t)r * 1536 + 512 + k;
        hsplit(enc_Whh0[i], &g_e0w1[o0], &g_e0w2[o0]);
        hsplit(dec_Whh0[i], &g_d0w1[o0], &g_d0w2[o0]);
        size_t o1 = (size_t)r * 2048 + k;
        hsplit(enc_Wih1[i], &g_e1w1[o1], &g_e1w2[o1]);
        hsplit(dec_Wih1[i], &g_d1w1[o1], &g_d1w2[o1]);
        size_t o2 = o1 + 1024;
        hsplit(enc_Whh1[i], &g_e1w1[o2], &g_e1w2[o2]);
        hsplit(dec_Whh1[i], &g_d1w1[o2], &g_d1w2[o2]);
    }
    for (int i = gid; i < 1024 * 1024; i += NBLK * NTHR)
        hsplit(dec_linW[i], &g_lnw1[i], &g_lnw2[i]);

    for (int i = gid; i < SRCL * BSZ * ED; i += NBLK * NTHR) {
        int step = i / (BSZ * ED);
        int r = i % (BSZ * ED);
        int b = r / ED, k = r % ED;
        int id = input_ids[b * SRCL + step];
        hsplit(enc_embed[(size_t)id * ED + k], &g_xe1[i], &g_xe2[i]);
    }
    if (bid == 0) {
        for (int i = t; i < BSZ * ED; i += NTHR) {
            int k = i % ED;
            hsplit(dec_embed[k], &g_xd1[i], &g_xd2[i]);
        }
    }
    for (int i = gid; i < BSZ * HD; i += NBLK * NTHR) {
        g_c0f[i] = 0.f; g_c1f[i] = 0.f;
        g_h0p1[i] = __half(0.f); g_h0p2[i] = __half(0.f);
        g_h1p1[i] = __half(0.f); g_h1p2[i] = __half(0.f);
    }
    gsync();

    const int jt = bid >> 2, ks = bid & 3;      // cells: 32 j-tiles x 4 k-splits
    const int jtL = bid >> 4, ksL = bid & 15;   // logits: 8 j-tiles x 16 k-splits

    // -------- encoder --------
    for (int ts = 0; ts < SRCL; ts++) {
        tc_gemm(g_e0w1, g_e0w2, 1536,
                g_xe1 + (size_t)ts * BSZ * ED, g_xe2 + (size_t)ts * BSZ * ED, ED,
                g_h0p1, g_h0p2, jt * 128, ks * 384, 6, NJ4,
                g_zpart + (size_t)ks * 64 * NJ4, su);
        gsync();
        gates_phase(g_zpart, enc_b0, g_c0f, g_h0p1, g_h0p2, bid);
        gsync();
        tc_gemm(g_e1w1, g_e1w2, 2048, g_h0p1, g_h0p2, HD, g_h1p1, g_h1p2,
                jt * 128, ks * 512, 8, NJ4, g_zpart + (size_t)ks * 64 * NJ4, su);
        gsync();
        gates_phase(g_zpart, enc_b1, g_c1f, g_h1p1, g_h1p2, bid);
        gsync();
    }

    // -------- decoder --------
    float* lg = (float*)(smem + OFF_LG);
    float* rv = (float*)(smem + OFF_RV);
    int*   ri = (int*)(smem + OFF_RI);
    float* rs = (float*)(smem + OFF_RS);

    for (int ts = 0; ts < TGTL; ts++) {
        tc_gemm(g_d0w1, g_d0w2, 1536, g_xd1, g_xd2, ED, g_h0p1, g_h0p2,
                jt * 128, ks * 384, 6, NJ4, g_zpart + (size_t)ks * 64 * NJ4, su);
        gsync();
        gates_phase(g_zpart, dec_b0, g_c0f, g_h0p1, g_h0p2, bid);
        gsync();
        tc_gemm(g_d1w1, g_d1w2, 2048, g_h0p1, g_h0p2, HD, g_h1p1, g_h1p2,
                jt * 128, ks * 512, 8, NJ4, g_zpart + (size_t)ks * 64 * NJ4, su);
        gsync();
        gates_phase(g_zpart, dec_b1, g_c1f, g_h1p1, g_h1p2, bid);
        gsync();
        tc_gemm(g_lnw1, g_lnw2, 1024, g_h1p1, g_h1p2, HD, g_h1p1, g_h1p2,
                jtL * 128, ksL * 64, 1, HD,
                g_zpart + (size_t)ksL * 64 * HD, su);
        gsync();

        if (bid < BSZ) {
            int b = bid;
#pragma unroll
            for (int i = 0; i < 2; i++) {
                int u = t + i * 512;
                float s = 0.f;
#pragma unroll
                for (int sp = 0; sp < 16; sp++)
                    s += g_zpart[((size_t)sp * 64 + b) * HD + u];
                lg[u] = s + dec_linb[u];
            }
            __syncthreads();
            float mv = lg[t]; int mi = t;
            {
                int u = t + 512;
                float v = lg[u];
                if (v > mv) { mv = v; mi = u; }
            }
            rv[t] = mv; ri[t] = mi;
            __syncthreads();
            for (int off = 256; off > 0; off >>= 1) {
                if (t < off) {
                    float vo = rv[t + off]; int io = ri[t + off];
                    if (vo > rv[t] || (vo == rv[t] && io < ri[t])) { rv[t] = vo; ri[t] = io; }
                }
                __syncthreads();
            }
            float m = rv[0];
            float ps = 0.f;
#pragma unroll
            for (int i = 0; i < 2; i++) ps += expf(lg[t + i * 512] - m);
            rs[t] = ps;
            __syncthreads();
            for (int off = 256; off > 0; off >>= 1) {
                if (t < off) rs[t] += rs[t + off];
                __syncthreads();
            }
            float lse = m + logf(rs[0]);
#pragma unroll
            for (int i = 0; i < 2; i++) {
                int u = t + i * 512;
                out[(size_t)ts * (BSZ * HD) + b * HD + u] = lg[u] - lse;
            }
            int mi0 = ri[0];
            for (int k = t; k < ED; k += NTHR)
                hsplit(dec_embed[(size_t)mi0 * ED + k], &g_xd1[b * ED + k], &g_xd2[b * ED + k]);
            if (t == 0) {
                int tg = tag_ids[b * TGTL + ts];
                g_nll[ts * BSZ + b] = (tg != 0) ? (lse - lg[tg]) : 0.0f;
            }
            __syncthreads();
        }
        gsync();
    }

    // -------- loss (block 0) --------
    if (bid == 0) {
        float* stepv = (float*)(smem + OFF_STEPV);
        if (t < TGTL) {
            int cnt = 0;
            float s = 0.f;
            for (int b = 0; b < BSZ; b++) {
                if (tag_ids[b * TGTL + t] != 0) cnt++;
                s += g_nll[t * BSZ + b];
            }
            stepv[t] = s / (float)(cnt > 0 ? cnt : 1);
        }
        __syncthreads();
        if (t == 0) {
            float total = 0.f;
            for (int i = 0; i < TGTL; i++) total += stepv[i];
            if (out_size > OUT_MAIN) out[OUT_MAIN] = total;
        }
    }
}

// ---------------- host launch: ONE graph node ----------------
extern "C" void kernel_launch(void* const* d_in, const int* in_sizes, int n_in,
                              void* d_out, int out_size) {
    cudaFuncSetAttribute(seq_main, cudaFuncAttributeMaxDynamicSharedMemorySize, SMEM_TOTAL);
    seq_main<<<NBLK, NTHR, SMEM_TOTAL>>>(
        (const int*)d_in[0], (const int*)d_in[1], (const float*)d_in[2],
        (const float*)d_in[3], (const float*)d_in[4], (const float*)d_in[5],
        (const float*)d_in[6], (const float*)d_in[7], (const float*)d_in[8],
        (const float*)d_in[9],
        (const float*)d_in[10], (const float*)d_in[11], (const float*)d_in[12],
        (const float*)d_in[13], (const float*)d_in[14], (const float*)d_in[15],
        (const float*)d_in[16], (const float*)d_in[17],
        (float*)d_out, out_size);
}